// round 8
// baseline (speedup 1.0000x reference)
#include <cuda_runtime.h>
#include <cuda_fp16.h>
#include <math.h>
#include <stdint.h>

#define BB 8
#define NN 4096
#define DD 512
#define TD 256
#define TOK (BB*NN)
#define SCALE_F 0.0625f

// ---------------- static scratch ----------------
__device__ __align__(16) __half g_ph[4][(size_t)TOK*DD];     // normalized q/k fp16 [qI,qM,kI,kM]
__device__ __align__(16) __half g_Wth[4][DD*DD];             // W^T fp16 [mat][n][k]
__device__ __align__(16) __half g_Wch[BB][TD*2048];          // combined W^T fp16 [b][n][k]
__device__ float g_fwT[TD*DD];                               // f_w^T [n][e]
__device__ float g_PFt[4][TD*DD];                            // (p_i@f_w)^T [n][k]
__device__ float g_acc[BB*2*513];
__device__ float g_cvec[TD];

// ---------------- helpers ----------------
__device__ __forceinline__ uint32_t smem_u32(const void* p) {
    uint32_t a;
    asm("{ .reg .u64 t; cvta.to.shared.u64 t, %1; cvt.u32.u64 %0, t; }" : "=r"(a) : "l"(p));
    return a;
}
__device__ __forceinline__ void cp16(uint32_t s, const void* g) {
    asm volatile("cp.async.cg.shared.global [%0], [%1], 16;" :: "r"(s), "l"(g));
}
__device__ __forceinline__ void cp_commit() { asm volatile("cp.async.commit_group;"); }
__device__ __forceinline__ void cp_wait1()  { asm volatile("cp.async.wait_group 1;"); }
__device__ __forceinline__ void cp_wait0()  { asm volatile("cp.async.wait_group 0;"); }
__device__ __forceinline__ void ldsm4(uint32_t* r, uint32_t addr) {
    asm volatile("ldmatrix.sync.aligned.m8n8.x4.shared.b16 {%0,%1,%2,%3}, [%4];"
        : "=r"(r[0]), "=r"(r[1]), "=r"(r[2]), "=r"(r[3]) : "r"(addr));
}
__device__ __forceinline__ void mma_f16(float* c, const uint32_t* a, uint32_t b0, uint32_t b1) {
    asm volatile("mma.sync.aligned.m16n8k16.row.col.f32.f16.f16.f32 "
        "{%0,%1,%2,%3}, {%4,%5,%6,%7}, {%8,%9}, {%0,%1,%2,%3};"
        : "+f"(c[0]), "+f"(c[1]), "+f"(c[2]), "+f"(c[3])
        : "r"(a[0]), "r"(a[1]), "r"(a[2]), "r"(a[3]), "r"(b0), "r"(b1));
}

// ================= fused projection kernel =================
// grid (TOK/64, 2)  y = I/M; 256 threads (8 warps, 2m x 4n)
// SMEM layout (bytes):
#define F_A   0          // 64 x 512 halves = 65536, row 1024B, swizzled
#define F_B   65536      // 2 bufs x 8192  (128 n-rows x 32 halves, paired-row swizzle)
#define F_O   81920      // 64 x 1024 halves, row stride 2064B = 132096
#define F_BQ  214016     // 512 floats
#define F_BK  216064
#define F_WG  218112
#define F_GU  220160     // 513 floats
#define F_TOTAL 222224

__global__ void __launch_bounds__(256) proj_fused(
    const float* __restrict__ xI, const float* __restrict__ xM,
    const float* __restrict__ bqI, const float* __restrict__ bqM,
    const float* __restrict__ bkI, const float* __restrict__ bkM,
    const float* __restrict__ wgI, const float* __restrict__ wgM)
{
    extern __shared__ char smem[];
    const uint32_t sb = smem_u32(smem);
    const int tid = threadIdx.x, wid = tid >> 5, lane = tid & 31;
    const int imsel = blockIdx.y;
    const int tok0 = blockIdx.x * 64;
    const int b = tok0 >> 12;
    const int matq = imsel, matk = 2 + imsel;

    float* sbq = (float*)(smem + F_BQ);
    float* sbk = (float*)(smem + F_BK);
    float* swg = (float*)(smem + F_WG);
    float* sGu = (float*)(smem + F_GU);
    {
        const float* bq = imsel ? bqM : bqI;
        const float* bk = imsel ? bkM : bkI;
        const float* wg = imsel ? wgM : wgI;
        sbq[tid] = bq[tid]; sbq[tid+256] = bq[tid+256];
        sbk[tid] = bk[tid]; sbk[tid+256] = bk[tid+256];
        swg[tid] = wg[tid]; swg[tid+256] = wg[tid+256];
        for (int c = tid; c < 513; c += 256) sGu[c] = 0.f;
    }

    // ---- issue B chunk for global chunk index g (8 tiles x 16 chunks) ----
    auto issue = [&](int g) {
        const int tile = g >> 4, c = g & 15, buf = g & 1;
        const int which = tile >> 2, nt = tile & 3;
        const __half* W = g_Wth[which ? matk : matq];
        const int n0 = nt * 128;
        #pragma unroll
        for (int it = 0; it < 2; it++) {
            int v = it*256 + tid;
            int rB = v >> 2, kb = v & 3;
            uint32_t u = ((rB & 1) << 2) | kb;
            uint32_t off = (rB >> 1)*128 + ((u ^ ((rB >> 1) & 7)) << 4);
            cp16(sb + F_B + buf*8192 + off,
                 W + (size_t)(n0 + rB)*512 + c*32 + kb*8);
        }
        cp_commit();
    };

    issue(0); issue(1);

    // ---- stage A: 64 tokens x 512 floats -> fp16 swizzled SMEM ----
    {
        const float* x = (imsel ? xM : xI) + (size_t)tok0 * 512;
        #pragma unroll
        for (int it = 0; it < 16; it++) {
            int v = it*256 + tid;
            int r = v >> 6, ku = v & 63;
            float4 f0 = *(const float4*)(x + (size_t)r*512 + ku*8);
            float4 f1 = *(const float4*)(x + (size_t)r*512 + ku*8 + 4);
            __half h[8];
            h[0]=__float2half(f0.x); h[1]=__float2half(f0.y);
            h[2]=__float2half(f0.z); h[3]=__float2half(f0.w);
            h[4]=__float2half(f1.x); h[5]=__float2half(f1.y);
            h[6]=__float2half(f1.z); h[7]=__float2half(f1.w);
            uint32_t up = (ku & 56) | ((ku & 7) ^ (r & 7));
            *(uint4*)(smem + F_A + r*1024 + (up << 4)) = *(uint4*)h;
        }
    }
    __syncthreads();

    const int wm = wid >> 2, wn = wid & 3;     // 2m x 4n warps
    const int mwb = wm*32, nwb = wn*32;

    float acc[2][4][4];
    #pragma unroll
    for (int mt = 0; mt < 2; mt++)
        #pragma unroll
        for (int n8 = 0; n8 < 4; n8++)
            #pragma unroll
            for (int e = 0; e < 4; e++) acc[mt][n8][e] = 0.f;

    for (int g = 0; g < 128; g++) {
        if (g < 127) cp_wait1(); else cp_wait0();
        __syncthreads();
        const int buf = g & 1, c = g & 15;
        const uint32_t bbase = sb + F_B + buf*8192;

        #pragma unroll
        for (int k16 = 0; k16 < 2; k16++) {
            uint32_t ah[2][4], bh[2][4];
            #pragma unroll
            for (int mt = 0; mt < 2; mt++) {
                int r = mwb + mt*16 + (lane & 15);
                int ku = c*4 + k16*2 + (lane >> 4);
                uint32_t up = (ku & 56) | ((ku & 7) ^ (r & 7));
                ldsm4(ah[mt], sb + F_A + r*1024 + (up << 4));
            }
            #pragma unroll
            for (int bt = 0; bt < 2; bt++) {
                int rB = nwb + bt*16 + ((lane >> 4) << 3) + (lane & 7);
                int kb = k16*2 + ((lane >> 3) & 1);
                uint32_t u = ((rB & 1) << 2) | kb;
                uint32_t off = (rB >> 1)*128 + ((u ^ ((rB >> 1) & 7)) << 4);
                ldsm4(bh[bt], bbase + off);
            }
            #pragma unroll
            for (int mt = 0; mt < 2; mt++)
                #pragma unroll
                for (int n8 = 0; n8 < 4; n8++) {
                    int bt = n8 >> 1, s = (n8 & 1)*2;
                    mma_f16(acc[mt][n8], ah[mt], bh[bt][s], bh[bt][s+1]);
                }
        }
        __syncthreads();
        if (g + 2 < 128) issue(g + 2);

        if ((g & 15) == 15) {   // tile done -> store to O with bias
            const int tile = g >> 4, which = tile >> 2, nt = tile & 3;
            const float* bb = which ? sbk : sbq;
            #pragma unroll
            for (int mt = 0; mt < 2; mt++) {
                int t0 = mwb + mt*16 + (lane >> 2);
                #pragma unroll
                for (int n8 = 0; n8 < 4; n8++) {
                    int gcol = nwb + n8*8 + 2*(lane & 3);
                    float b0 = bb[nt*128 + gcol], b1 = bb[nt*128 + gcol + 1];
                    int col = which*512 + nt*128 + gcol;
                    *(__half2*)(smem + F_O + t0*2064 + col*2) =
                        __floats2half2_rn(acc[mt][n8][0] + b0, acc[mt][n8][1] + b1);
                    *(__half2*)(smem + F_O + (t0+8)*2064 + col*2) =
                        __floats2half2_rn(acc[mt][n8][2] + b0, acc[mt][n8][3] + b1);
                    acc[mt][n8][0] = acc[mt][n8][1] = acc[mt][n8][2] = acc[mt][n8][3] = 0.f;
                }
            }
        }
    }
    __syncthreads();

    // ---- in-SMEM normalize + s + Gu ----
    {
        float gu[16];
        #pragma unroll
        for (int j = 0; j < 16; j++) gu[j] = 0.f;
        float s2acc = 0.f;
        float wgv[16];
        #pragma unroll
        for (int j = 0; j < 16; j++) wgv[j] = swg[lane*16 + j];

        for (int tt = 0; tt < 8; tt++) {
            int t = wid*8 + tt;
            size_t gbase = (size_t)(tok0 + t) * 512 + lane*16;
            // ---- q ----
            {
                uint4 d0 = *(uint4*)(smem + F_O + t*2064 + lane*32);
                uint4 d1 = *(uint4*)(smem + F_O + t*2064 + lane*32 + 16);
                __half2* hp0 = (__half2*)&d0; __half2* hp1 = (__half2*)&d1;
                float v[16];
                #pragma unroll
                for (int j = 0; j < 4; j++) {
                    float2 f0 = __half22float2(hp0[j]);
                    float2 f1 = __half22float2(hp1[j]);
                    v[j*2] = f0.x; v[j*2+1] = f0.y;
                    v[8+j*2] = f1.x; v[8+j*2+1] = f1.y;
                }
                float ss = 0.f;
                #pragma unroll
                for (int j = 0; j < 16; j++) ss += v[j]*v[j];
                #pragma unroll
                for (int o = 16; o; o >>= 1) ss += __shfl_xor_sync(0xFFFFFFFFu, ss, o);
                float inv = 1.f / fmaxf(sqrtf(ss), 1e-12f);
                float sp = 0.f;
                #pragma unroll
                for (int j = 0; j < 16; j++) { v[j] *= inv; sp += v[j]*wgv[j]; }
                #pragma unroll
                for (int o = 16; o; o >>= 1) sp += __shfl_xor_sync(0xFFFFFFFFu, sp, o);
                uint32_t hw[8];
                #pragma unroll
                for (int j = 0; j < 8; j++) {
                    __half2 p = __floats2half2_rn(v[j*2], v[j*2+1]);
                    hw[j] = *(uint32_t*)&p;
                }
                *(uint4*)(&g_ph[matq][gbase])     = *(uint4*)&hw[0];
                *(uint4*)(&g_ph[matq][gbase + 8]) = *(uint4*)&hw[4];
                #pragma unroll
                for (int j = 0; j < 16; j++) gu[j] += sp * v[j];
                s2acc += sp * sp;
            }
            // ---- k ----
            {
                uint4 d0 = *(uint4*)(smem + F_O + t*2064 + 1024 + lane*32);
                uint4 d1 = *(uint4*)(smem + F_O + t*2064 + 1024 + lane*32 + 16);
                __half2* hp0 = (__half2*)&d0; __half2* hp1 = (__half2*)&d1;
                float v[16];
                #pragma unroll
                for (int j = 0; j < 4; j++) {
                    float2 f0 = __half22float2(hp0[j]);
                    float2 f1 = __half22float2(hp1[j]);
                    v[j*2] = f0.x; v[j*2+1] = f0.y;
                    v[8+j*2] = f1.x; v[8+j*2+1] = f1.y;
                }
                float ss = 0.f;
                #pragma unroll
                for (int j = 0; j < 16; j++) ss += v[j]*v[j];
                #pragma unroll
                for (int o = 16; o; o >>= 1) ss += __shfl_xor_sync(0xFFFFFFFFu, ss, o);
                float inv = 1.f / fmaxf(sqrtf(ss), 1e-12f);
                uint32_t hw[8];
                #pragma unroll
                for (int j = 0; j < 8; j++) {
                    __half2 p = __floats2half2_rn(v[j*2]*inv, v[j*2+1]*inv);
                    hw[j] = *(uint32_t*)&p;
                }
                *(uint4*)(&g_ph[matk][gbase])     = *(uint4*)&hw[0];
                *(uint4*)(&g_ph[matk][gbase + 8]) = *(uint4*)&hw[4];
            }
        }
        #pragma unroll
        for (int j = 0; j < 16; j++) atomicAdd(&sGu[lane*16 + j], gu[j]);
        if (lane == 0) atomicAdd(&sGu[512], s2acc);
    }
    __syncthreads();
    {
        float* accG = g_acc + ((size_t)b*2 + imsel)*513;
        for (int c = tid; c < 513; c += 256) atomicAdd(&accG[c], sGu[c]);
    }
}

// ================= final GEMM: out = [kI|kM|qI|qM] @ Wc + cvec =================
#define BUFSZ 32768
#define SMEM_F 65536

__global__ void __launch_bounds__(256) gemm_final(float* __restrict__ outp)
{
    extern __shared__ char smem[];
    const uint32_t sb = smem_u32(smem);
    __shared__ float sbias[128];

    const int tid = threadIdx.x, wid = tid >> 5, lane = tid & 31;
    const int tok0 = blockIdx.x * 128;
    const int n0   = blockIdx.y * 128;
    const int batch = tok0 >> 12;
    const int NC = 32;

    if (tid < 128) sbias[tid] = g_cvec[n0 + tid];

    auto issue = [&](int c, int buf) {
        uint32_t abase = sb + buf*BUFSZ;
        uint32_t bbase = abase + 16384;
        #pragma unroll
        for (int it = 0; it < 4; it++) {
            int v = it*256 + tid;
            int r = v >> 3, u = v & 7;
            int mat = (c >> 3) ^ 2;     // k-segs: kI,kM,qI,qM -> mats 2,3,0,1
            cp16(abase + r*128 + ((u ^ (r & 7)) << 4),
                 g_ph[mat] + (size_t)(tok0 + r)*512 + (c & 7)*64 + u*8);
        }
        #pragma unroll
        for (int it = 0; it < 4; it++) {
            int v = it*256 + tid;
            int r = v >> 3, u = v & 7;
            cp16(bbase + r*128 + ((u ^ (r & 7)) << 4),
                 g_Wch[batch] + (size_t)(n0 + r)*2048 + c*64 + u*8);
        }
        cp_commit();
    };

    float acc[2][8][4];
    #pragma unroll
    for (int mt = 0; mt < 2; mt++)
        #pragma unroll
        for (int nt = 0; nt < 8; nt++)
            #pragma unroll
            for (int e = 0; e < 4; e++) acc[mt][nt][e] = 0.f;

    const int wm = wid >> 1, wn = wid & 1;
    const int mwb = wm*32, nwb = wn*64;

    issue(0, 0);
    issue(1, 1);

    for (int c = 0; c < NC; c++) {
        if (c < NC - 1) cp_wait1(); else cp_wait0();
        __syncthreads();
        const int buf = c & 1;
        uint32_t abase = sb + buf*BUFSZ;
        uint32_t bbase = abase + 16384;

        #pragma unroll
        for (int k16 = 0; k16 < 4; k16++) {
            uint32_t ah[2][4], bh[4][4];
            #pragma unroll
            for (int mt = 0; mt < 2; mt++) {
                int row = mwb + mt*16 + (lane & 15);
                int kb  = k16*2 + (lane >> 4);
                ldsm4(ah[mt], abase + row*128 + ((kb ^ (row & 7)) << 4));
            }
            #pragma unroll
            for (int bt = 0; bt < 4; bt++) {
                int row = nwb + bt*16 + ((lane >> 4) << 3) + (lane & 7);
                int kb  = k16*2 + ((lane >> 3) & 1);
                ldsm4(bh[bt], bbase + row*128 + ((kb ^ (row & 7)) << 4));
            }
            #pragma unroll
            for (int mt = 0; mt < 2; mt++)
                #pragma unroll
                for (int nt = 0; nt < 8; nt++) {
                    int bt = nt >> 1, s = (nt & 1)*2;
                    mma_f16(acc[mt][nt], ah[mt], bh[bt][s], bh[bt][s+1]);
                }
        }
        __syncthreads();
        if (c + 2 < NC) issue(c + 2, buf);
    }

    #pragma unroll
    for (int mt = 0; mt < 2; mt++) {
        int row = tok0 + mwb + mt*16 + (lane >> 2);
        #pragma unroll
        for (int nt = 0; nt < 8; nt++) {
            int col = n0 + nwb + nt*8 + 2*(lane & 3);
            float b0 = sbias[col - n0], b1 = sbias[col - n0 + 1];
            *(float2*)(outp + (size_t)row*256 + col) =
                make_float2(acc[mt][nt][0] + b0, acc[mt][nt][1] + b1);
            *(float2*)(outp + (size_t)(row+8)*256 + col) =
                make_float2(acc[mt][nt][2] + b0, acc[mt][nt][3] + b1);
        }
    }
}

// ---------------- prep: W^T fp16, f_w^T, zero acc ----------------
__global__ void prep_kernel(const float* __restrict__ wqI, const float* __restrict__ wqM,
                            const float* __restrict__ wkI, const float* __restrict__ wkM,
                            const float* __restrict__ fw)
{
    int idx = blockIdx.x*256 + threadIdx.x;
    if (idx < 4*DD*DD) {
        int m = idx >> 18, r = idx & (DD*DD - 1);
        int n = r >> 9, k = r & 511;
        const float* W = (m==0)?wqI:(m==1)?wqM:(m==2)?wkI:wkM;
        g_Wth[m][r] = __float2half(W[(size_t)k*DD + n]);
    } else if ((idx -= 4*DD*DD) < TD*DD) {
        int n = idx >> 9, e = idx & 511;
        g_fwT[idx] = fw[(size_t)e*TD + n];
    } else if ((idx -= TD*DD) < BB*2*513) {
        g_acc[idx] = 0.f;
    }
}

// ---------------- PFt = (p_i @ f_w)^T ----------------
__global__ void __launch_bounds__(256) pf_kernel(
    const float* __restrict__ p1, const float* __restrict__ p2,
    const float* __restrict__ p3, const float* __restrict__ p4,
    const float* __restrict__ fw)
{
    const float* P[4] = {p1, p2, p3, p4};
    const float* p = P[blockIdx.y];
    float* out = g_PFt[blockIdx.y];
    const int r0 = blockIdx.x * 32;
    __shared__ float sA[32][8];
    __shared__ float sF[8][256];
    const int warp = threadIdx.x >> 5, lane = threadIdx.x & 31;
    float acc[4][8];
    #pragma unroll
    for (int i = 0; i < 4; i++)
        #pragma unroll
        for (int j = 0; j < 8; j++) acc[i][j] = 0.f;
    for (int k0 = 0; k0 < DD; k0 += 8) {
        {
            int t = threadIdx.x >> 3, kk = threadIdx.x & 7;
            sA[t][kk] = p[(size_t)(r0 + t)*DD + k0 + kk];
        }
        #pragma unroll
        for (int i = 0; i < 2; i++) {
            int idx = threadIdx.x + 256*i;
            int kk = idx >> 6, dv = idx & 63;
            ((float4*)&sF[kk][0])[dv] = ((const float4*)(fw + (size_t)(k0+kk)*TD))[dv];
        }
        __syncthreads();
        #pragma unroll
        for (int kk = 0; kk < 8; kk++) {
            float a0 = sA[4*warp+0][kk], a1 = sA[4*warp+1][kk];
            float a2 = sA[4*warp+2][kk], a3 = sA[4*warp+3][kk];
            #pragma unroll
            for (int j = 0; j < 8; j++) {
                float w = sF[kk][lane + 32*j];
                acc[0][j] += a0*w; acc[1][j] += a1*w;
                acc[2][j] += a2*w; acc[3][j] += a3*w;
            }
        }
        __syncthreads();
    }
    #pragma unroll
    for (int i = 0; i < 4; i++)
        #pragma unroll
        for (int j = 0; j < 8; j++)
            out[(size_t)(lane + 32*j)*DD + r0 + 4*warp + i] = acc[i][j];
}

// ---------------- cvec ----------------
__global__ void cvec_kernel(const float* __restrict__ b1, const float* __restrict__ b2,
                            const float* __restrict__ b3, const float* __restrict__ b4,
                            const float* __restrict__ fb)
{
    int c = blockIdx.x, t = threadIdx.x;
    float p = 0.f;
    for (int e = t; e < DD; e += 128)
        p += (b1[e] + b2[e] + b3[e] + b4[e]) * g_fwT[(size_t)c*DD + e];
    #pragma unroll
    for (int o = 16; o; o >>= 1) p += __shfl_xor_sync(0xFFFFFFFFu, p, o);
    __shared__ float sp[4];
    if ((t & 31) == 0) sp[t >> 5] = p;
    __syncthreads();
    if (t == 0) g_cvec[c] = sp[0] + sp[1] + sp[2] + sp[3] + fb[c];
}

// ---------------- combined weights Wc^T fp16 ----------------
// K segs (2048): [0,512)=kI, [512,1024)=kM, [1024,1536)=qI (f_w), [1536,2048)=qM (f_w)
__global__ void combine_kernel()
{
    int n = blockIdx.x, b = blockIdx.y, t = threadIdx.x;
    const float* acc = g_acc + (size_t)b*2*513;
    float nI = fmaxf(SCALE_F * sqrtf(acc[512]),       1e-12f);
    float nM = fmaxf(SCALE_F * sqrtf(acc[513 + 512]), 1e-12f);
    for (int k = t; k < 2048; k += 256) {
        float v;
        if (k < 1024) {
            int kk = k & 511;
            float GI = SCALE_F * acc[kk] / nI;
            float GM = SCALE_F * acc[513 + kk] / nM;
            if (k < 512) v = GI*g_PFt[0][(size_t)n*DD+kk] + GM*g_PFt[3][(size_t)n*DD+kk];
            else         v = GI*g_PFt[1][(size_t)n*DD+kk] + GM*g_PFt[2][(size_t)n*DD+kk];
        } else {
            v = g_fwT[(size_t)n*DD + (k & 511)];
        }
        g_Wch[b][(size_t)n*2048 + k] = __float2half(v);
    }
}

// ---------------- launch ----------------
extern "C" void kernel_launch(void* const* d_in, const int* in_sizes, int n_in,
                              void* d_out, int out_size)
{
    const float* xI  = (const float*)d_in[0];
    const float* xM  = (const float*)d_in[1];
    const float* wqI = (const float*)d_in[2];
    const float* bqI = (const float*)d_in[3];
    const float* wkI = (const float*)d_in[4];
    const float* bkI = (const float*)d_in[5];
    const float* wqM = (const float*)d_in[6];
    const float* bqM = (const float*)d_in[7];
    const float* wkM = (const float*)d_in[8];
    const float* bkM = (const float*)d_in[9];
    const float* wgI = (const float*)d_in[10];
    const float* wgM = (const float*)d_in[11];
    const float* p1w = (const float*)d_in[12];
    const float* p1b = (const float*)d_in[13];
    const float* p2w = (const float*)d_in[14];
    const float* p2b = (const float*)d_in[15];
    const float* p3w = (const float*)d_in[16];
    const float* p3b = (const float*)d_in[17];
    const float* p4w = (const float*)d_in[18];
    const float* p4b = (const float*)d_in[19];
    const float* fw  = (const float*)d_in[20];
    const float* fb  = (const float*)d_in[21];
    float* out = (float*)d_out;

    cudaFuncSetAttribute(proj_fused, cudaFuncAttributeMaxDynamicSharedMemorySize, F_TOTAL);
    cudaFuncSetAttribute(gemm_final, cudaFuncAttributeMaxDynamicSharedMemorySize, SMEM_F);

    prep_kernel<<<4642, 256>>>(wqI, wqM, wkI, wkM, fw);
    proj_fused<<<dim3(TOK/64, 2), 256, F_TOTAL>>>(xI, xM, bqI, bqM, bkI, bkM, wgI, wgM);
    pf_kernel<<<dim3(16, 4), 256>>>(p1w, p2w, p3w, p4w, fw);
    cvec_kernel<<<TD, 128>>>(p1b, p2b, p3b, p4b, fb);
    combine_kernel<<<dim3(TD, BB), 256>>>();
    gemm_final<<<dim3(TOK/128, 2), 256, SMEM_F>>>(out);
}